// round 8
// baseline (speedup 1.0000x reference)
#include <cuda_runtime.h>

// ---------------- problem constants ----------------
constexpr int Bn = 32;
constexpr int Pn = 16384;
constexpr int Kn = 64;
constexpr int NTILES = 16;           // 64-row tiles per CTA (single-wave grid)
constexpr int RPC = 64 * NTILES;     // 1024 rows per CTA
constexpr int NRB = Pn / RPC;        // 16 row-blocks per batch -> grid 512
constexpr int MAXIT = 50;
constexpr int NSIT = 8;

// ---------------- device scratch (static; no allocations) ----------------
__device__ float g_W[(size_t)Bn * Pn * Kn];            // 128 MB: current Y' ("W")
__device__ float g_Gpart[(size_t)Bn * NRB * Kn * Kn];  // 8 MB: per-CTA Gram partials
__device__ float g_A[Bn * Kn * Kn];                    // 0.5*(I+S) per batch

// ---------------- packed f32x2 helpers ----------------
typedef unsigned long long f2_t;

__device__ __forceinline__ f2_t pack2(float lo, float hi) {
    f2_t r; asm("mov.b64 %0, {%1, %2};" : "=l"(r) : "f"(lo), "f"(hi)); return r;
}
__device__ __forceinline__ void unpack2(f2_t v, float& lo, float& hi) {
    asm("mov.b64 {%0, %1}, %2;" : "=f"(lo), "=f"(hi) : "l"(v));
}
__device__ __forceinline__ void ffma2(f2_t& d, f2_t a, f2_t b) {
    asm("fma.rn.f32x2 %0, %1, %2, %0;" : "+l"(d) : "l"(a), "l"(b));
}
__device__ __forceinline__ float lane_of(const float4& v, int kk) {
    return (kk == 0) ? v.x : (kk == 1) ? v.y : (kk == 2) ? v.z : v.w;
}

// ============================================================================
// Big fused kernel.
// MODE 0 (INIT):  W = X0 (copy), Gram partials of W.
// MODE 1 (MID):   Z = relu(W @ A); W' = Z - 0.1*(Z - X0); store W'; Gram(W').
// MODE 2 (FINAL): Z = relu(W @ A); store Z to d_out. No gram.
// 128 threads. Matmul: thread owns 4 rows x 8 cols of the 64x64 tile.
// Gram: thread owns 4 a-cols x 8 b-cols, accumulated over all 16 tiles.
// ============================================================================
template <int MODE>
__global__ __launch_bounds__(128) void ac_kernel(const float* __restrict__ x0,
                                                 float* __restrict__ gout) {
    const int b = blockIdx.y, rb = blockIdx.x;
    const int tid = threadIdx.x;
    const int tx = tid & 7, ty = tid >> 3;
    const int c0 = tx * 8;   // matmul cols / gram b-cols
    const int r0 = ty * 4;   // matmul rows / gram a-cols

    __shared__ float sW[64][68];
    __shared__ float sA[64][68];

    const size_t baseRow = (size_t)b * Pn + (size_t)rb * RPC;

    if (MODE != 0) {
        const float4* Ag = (const float4*)(g_A + b * 4096);
        #pragma unroll
        for (int i = tid; i < 1024; i += 128) {
            float4 v = Ag[i];
            *(float4*)&sA[i >> 4][(i & 15) * 4] = v;
        }
    }

    f2_t gacc[4][4];
    #pragma unroll
    for (int i = 0; i < 4; i++)
        #pragma unroll
        for (int j = 0; j < 4; j++) gacc[i][j] = pack2(0.f, 0.f);

    for (int tile = 0; tile < NTILES; ++tile) {
        const size_t trow = baseRow + (size_t)tile * 64;
        __syncthreads();  // previous-tile smem reads complete
        {
            const float* wsrcp = (MODE == 0 ? x0 : (const float*)g_W) + trow * 64;
            const float4* src = (const float4*)wsrcp;
            float4* wdst = (float4*)(g_W + trow * 64);
            #pragma unroll
            for (int i = tid; i < 1024; i += 128) {
                float4 v = src[i];
                *(float4*)&sW[i >> 4][(i & 15) * 4] = v;
                if (MODE == 0) wdst[i] = v;
            }
        }
        __syncthreads();

        if (MODE != 0) {
            // Prefetch X0 epilogue operands BEFORE the matmul so the LDG
            // latency is hidden under ~2048 cycles of FFMA2 (MODE 1 only).
            float4 xpre[4][2];
            if (MODE == 1) {
                #pragma unroll
                for (int i = 0; i < 4; i++) {
                    const float* xr = x0 + (trow + r0 + i) * 64 + c0;
                    xpre[i][0] = *(const float4*)xr;
                    xpre[i][1] = *(const float4*)(xr + 4);
                }
            }

            // ---- Z-block = (W tile) @ A, thread block 4x8, packed f32x2 ----
            // k-blocked by 4: vector loads on BOTH operands.
            f2_t acc[4][4];
            #pragma unroll
            for (int i = 0; i < 4; i++)
                #pragma unroll
                for (int j = 0; j < 4; j++) acc[i][j] = pack2(0.f, 0.f);

            #pragma unroll 2
            for (int kb = 0; kb < 16; kb++) {
                float4 w4[4];
                #pragma unroll
                for (int i = 0; i < 4; i++)
                    w4[i] = *(const float4*)&sW[r0 + i][kb * 4];
                #pragma unroll
                for (int kk = 0; kk < 4; kk++) {
                    const int k = kb * 4 + kk;
                    float4 a0 = *(const float4*)&sA[k][c0];
                    float4 a1 = *(const float4*)&sA[k][c0 + 4];
                    f2_t pb0 = pack2(a0.x, a0.y), pb1 = pack2(a0.z, a0.w);
                    f2_t pb2 = pack2(a1.x, a1.y), pb3 = pack2(a1.z, a1.w);
                    #pragma unroll
                    for (int i = 0; i < 4; i++) {
                        float w = lane_of(w4[i], kk);
                        f2_t wp = pack2(w, w);
                        ffma2(acc[i][0], wp, pb0);
                        ffma2(acc[i][1], wp, pb1);
                        ffma2(acc[i][2], wp, pb2);
                        ffma2(acc[i][3], wp, pb3);
                    }
                }
            }

            float wout[4][8];
            #pragma unroll
            for (int i = 0; i < 4; i++) {
                float z[8];
                unpack2(acc[i][0], z[0], z[1]); unpack2(acc[i][1], z[2], z[3]);
                unpack2(acc[i][2], z[4], z[5]); unpack2(acc[i][3], z[6], z[7]);
                #pragma unroll
                for (int j = 0; j < 8; j++) z[j] = fmaxf(z[j], 0.f);
                if (MODE == 1) {
                    float xv[8] = {xpre[i][0].x, xpre[i][0].y, xpre[i][0].z, xpre[i][0].w,
                                   xpre[i][1].x, xpre[i][1].y, xpre[i][1].z, xpre[i][1].w};
                    #pragma unroll
                    for (int j = 0; j < 8; j++)
                        wout[i][j] = z[j] - 0.1f * (z[j] - xv[j]);  // grad step
                } else {
                    #pragma unroll
                    for (int j = 0; j < 8; j++) wout[i][j] = z[j];
                }
            }

            __syncthreads();  // all matmul reads of sW done
            if (MODE == 1) {
                #pragma unroll
                for (int i = 0; i < 4; i++) {
                    float4 v0 = make_float4(wout[i][0], wout[i][1], wout[i][2], wout[i][3]);
                    float4 v1 = make_float4(wout[i][4], wout[i][5], wout[i][6], wout[i][7]);
                    *(float4*)&sW[r0 + i][c0] = v0;
                    *(float4*)&sW[r0 + i][c0 + 4] = v1;
                    float* wr = g_W + (trow + r0 + i) * 64 + c0;
                    *(float4*)wr = v0;
                    *(float4*)(wr + 4) = v1;
                }
                __syncthreads();  // W' visible in smem for gram
            } else {  // FINAL: write output
                #pragma unroll
                for (int i = 0; i < 4; i++) {
                    float* orow = gout + (trow + r0 + i) * 64 + c0;
                    *(float4*)orow = make_float4(wout[i][0], wout[i][1], wout[i][2], wout[i][3]);
                    *(float4*)(orow + 4) = make_float4(wout[i][4], wout[i][5], wout[i][6], wout[i][7]);
                }
            }
        }

        if (MODE != 2) {
            // ---- Gram accumulate over this tile: M[a][b] += sum_r W'[r][a]*W'[r][b]
            #pragma unroll 4
            for (int r = 0; r < 64; r++) {
                float4 wa  = *(const float4*)&sW[r][r0];
                float4 wb0 = *(const float4*)&sW[r][c0];
                float4 wb1 = *(const float4*)&sW[r][c0 + 4];
                f2_t pb0 = pack2(wb0.x, wb0.y), pb1 = pack2(wb0.z, wb0.w);
                f2_t pb2 = pack2(wb1.x, wb1.y), pb3 = pack2(wb1.z, wb1.w);
                float av[4] = {wa.x, wa.y, wa.z, wa.w};
                #pragma unroll
                for (int i = 0; i < 4; i++) {
                    f2_t ap = pack2(av[i], av[i]);
                    ffma2(gacc[i][0], ap, pb0);
                    ffma2(gacc[i][1], ap, pb1);
                    ffma2(gacc[i][2], ap, pb2);
                    ffma2(gacc[i][3], ap, pb3);
                }
            }
        }
    }

    if (MODE != 2) {
        float* gp = g_Gpart + ((size_t)(b * NRB + rb)) * 4096;
        #pragma unroll
        for (int i = 0; i < 4; i++) {
            float v[8];
            unpack2(gacc[i][0], v[0], v[1]); unpack2(gacc[i][1], v[2], v[3]);
            unpack2(gacc[i][2], v[4], v[5]); unpack2(gacc[i][3], v[6], v[7]);
            float* row = gp + (r0 + i) * 64 + c0;
            *(float4*)row = make_float4(v[0], v[1], v[2], v[3]);
            *(float4*)(row + 4) = make_float4(v[4], v[5], v[6], v[7]);
        }
    }
}

// ============================================================================
// Tiny per-batch kernel: reduce Gram partials (fixed order -> deterministic),
// Newton-Schulz inverse sqrt, emit A = 0.5*(I + S). 32 CTAs x 256 threads.
// Fusions (all exact):
//   it 0: Z0 = I  => T = 1.5I - 0.5*Y0 elementwise, Z1 = T, Y1 = Y0@T (1 mm)
//   it >=1: T = 1.5I - 0.5*(Z@Y) fused in one pass (T distinct buffer: 1 sync);
//           Y<-Y@T and Z<-T@Z fused in one dual pass (2 syncs, 2x ILP).
//   last it: Y update dead (only Z feeds output) -> plain Z<-T@Z.
// ============================================================================

// T = 1.5*I - 0.5*(Z@Y). T distinct from Z,Y -> single trailing sync.
__device__ __forceinline__ void mm_fusedT(float* __restrict__ T,
                                          const float* __restrict__ Z,
                                          const float* __restrict__ Y, int tid) {
    const int tx = tid & 15, ty = tid >> 4;
    const int c0 = tx * 4, r0 = ty * 4;
    f2_t acc[4][2];
    #pragma unroll
    for (int i = 0; i < 4; i++) { acc[i][0] = pack2(0.f, 0.f); acc[i][1] = pack2(0.f, 0.f); }
    #pragma unroll 2
    for (int kb = 0; kb < 16; kb++) {
        float4 a4[4];
        #pragma unroll
        for (int i = 0; i < 4; i++)
            a4[i] = *(const float4*)&Z[(r0 + i) * 64 + kb * 4];
        #pragma unroll
        for (int kk = 0; kk < 4; kk++) {
            float4 b4 = *(const float4*)&Y[(kb * 4 + kk) * 64 + c0];
            f2_t pb0 = pack2(b4.x, b4.y), pb1 = pack2(b4.z, b4.w);
            #pragma unroll
            for (int i = 0; i < 4; i++) {
                float a = lane_of(a4[i], kk);
                f2_t ap = pack2(a, a);
                ffma2(acc[i][0], ap, pb0);
                ffma2(acc[i][1], ap, pb1);
            }
        }
    }
    #pragma unroll
    for (int i = 0; i < 4; i++) {
        float v0, v1, v2, v3;
        unpack2(acc[i][0], v0, v1); unpack2(acc[i][1], v2, v3);
        const int row = r0 + i;
        v0 = ((row == c0 + 0) ? 1.5f : 0.f) - 0.5f * v0;
        v1 = ((row == c0 + 1) ? 1.5f : 0.f) - 0.5f * v1;
        v2 = ((row == c0 + 2) ? 1.5f : 0.f) - 0.5f * v2;
        v3 = ((row == c0 + 3) ? 1.5f : 0.f) - 0.5f * v3;
        *(float4*)&T[row * 64 + c0] = make_float4(v0, v1, v2, v3);
    }
    __syncthreads();
}

// Dual in-place update: Y <- Y@T and Z <- T@Z (independent products, shared pass).
// If WITH_Y == false, only Z is updated.
template <bool WITH_Y>
__device__ __forceinline__ void mm_dual(float* __restrict__ Y, float* __restrict__ Z,
                                        const float* __restrict__ T, int tid) {
    const int tx = tid & 15, ty = tid >> 4;
    const int c0 = tx * 4, r0 = ty * 4;
    f2_t accY[4][2], accZ[4][2];
    #pragma unroll
    for (int i = 0; i < 4; i++) {
        accY[i][0] = pack2(0.f, 0.f); accY[i][1] = pack2(0.f, 0.f);
        accZ[i][0] = pack2(0.f, 0.f); accZ[i][1] = pack2(0.f, 0.f);
    }
    #pragma unroll 2
    for (int kb = 0; kb < 16; kb++) {
        float4 aY[4], aZ[4];
        #pragma unroll
        for (int i = 0; i < 4; i++) {
            if (WITH_Y) aY[i] = *(const float4*)&Y[(r0 + i) * 64 + kb * 4];
            aZ[i] = *(const float4*)&T[(r0 + i) * 64 + kb * 4];
        }
        #pragma unroll
        for (int kk = 0; kk < 4; kk++) {
            const int k = kb * 4 + kk;
            float4 bZ = *(const float4*)&Z[k * 64 + c0];
            f2_t zb0 = pack2(bZ.x, bZ.y), zb1 = pack2(bZ.z, bZ.w);
            f2_t yb0, yb1;
            if (WITH_Y) {
                float4 bY = *(const float4*)&T[k * 64 + c0];
                yb0 = pack2(bY.x, bY.y); yb1 = pack2(bY.z, bY.w);
            }
            #pragma unroll
            for (int i = 0; i < 4; i++) {
                float az = lane_of(aZ[i], kk);
                f2_t azp = pack2(az, az);
                ffma2(accZ[i][0], azp, zb0);
                ffma2(accZ[i][1], azp, zb1);
                if (WITH_Y) {
                    float ay = lane_of(aY[i], kk);
                    f2_t ayp = pack2(ay, ay);
                    ffma2(accY[i][0], ayp, yb0);
                    ffma2(accY[i][1], ayp, yb1);
                }
            }
        }
    }
    __syncthreads();  // all reads of Y,Z,T done before in-place writes
    #pragma unroll
    for (int i = 0; i < 4; i++) {
        float v0, v1, v2, v3;
        unpack2(accZ[i][0], v0, v1); unpack2(accZ[i][1], v2, v3);
        *(float4*)&Z[(r0 + i) * 64 + c0] = make_float4(v0, v1, v2, v3);
        if (WITH_Y) {
            unpack2(accY[i][0], v0, v1); unpack2(accY[i][1], v2, v3);
            *(float4*)&Y[(r0 + i) * 64 + c0] = make_float4(v0, v1, v2, v3);
        }
    }
    __syncthreads();
}

__global__ __launch_bounds__(256) void ns_kernel() {
    const int b = blockIdx.x;
    const int tid = threadIdx.x;
    __shared__ float sY[4096];
    __shared__ float sZ[4096];
    __shared__ float sT[4096];  // exactly 48 KB total

    // deterministic partial reduction over 16 row-block partials (float4-wide)
    {
        const float4* gp = (const float4*)(g_Gpart + (size_t)b * NRB * 4096);
        float4* y4 = (float4*)sY;
        for (int idx = tid; idx < 1024; idx += 256) {
            float4 s = make_float4(0.f, 0.f, 0.f, 0.f);
            #pragma unroll
            for (int j = 0; j < NRB; j++) {
                float4 v = gp[(size_t)j * 1024 + idx];
                s.x += v.x; s.y += v.y; s.z += v.z; s.w += v.w;
            }
            y4[idx] = s;
        }
    }
    __syncthreads();

    // trace -> nrm
    float tr = (tid < 64) ? sY[tid * 64 + tid] : 0.f;
    #pragma unroll
    for (int o = 16; o > 0; o >>= 1) tr += __shfl_down_sync(0xffffffffu, tr, o);
    if ((tid & 31) == 0) sT[tid >> 5] = tr;
    __syncthreads();
    const float nrm = sT[0] + sT[1] + sT[2] + sT[3] + sT[4] + sT[5] + sT[6] + sT[7] + 1e-8f;
    __syncthreads();

    // Y0 = M/nrm; iteration 0 shortcut: T = 1.5I - 0.5*Y0 (Z0 = I), Z1 = T
    const float inv = 1.0f / nrm;
    for (int idx = tid; idx < 4096; idx += 256) {
        float y0 = sY[idx] * inv;
        sY[idx] = y0;
        float t0 = (((idx >> 6) == (idx & 63)) ? 1.5f : 0.f) - 0.5f * y0;
        sT[idx] = t0;
        sZ[idx] = t0;
    }
    __syncthreads();
    // Y1 = Y0@T (in place): plain single product.
    {
        const int tx = tid & 15, ty = tid >> 4;
        const int c0 = tx * 4, r0 = ty * 4;
        f2_t acc[4][2];
        #pragma unroll
        for (int i = 0; i < 4; i++) { acc[i][0] = pack2(0.f, 0.f); acc[i][1] = pack2(0.f, 0.f); }
        #pragma unroll 2
        for (int kb = 0; kb < 16; kb++) {
            float4 a4[4];
            #pragma unroll
            for (int i = 0; i < 4; i++)
                a4[i] = *(const float4*)&sY[(r0 + i) * 64 + kb * 4];
            #pragma unroll
            for (int kk = 0; kk < 4; kk++) {
                float4 b4 = *(const float4*)&sT[(kb * 4 + kk) * 64 + c0];
                f2_t pb0 = pack2(b4.x, b4.y), pb1 = pack2(b4.z, b4.w);
                #pragma unroll
                for (int i = 0; i < 4; i++) {
                    float a = lane_of(a4[i], kk);
                    f2_t ap = pack2(a, a);
                    ffma2(acc[i][0], ap, pb0);
                    ffma2(acc[i][1], ap, pb1);
                }
            }
        }
        __syncthreads();
        #pragma unroll
        for (int i = 0; i < 4; i++) {
            float v0, v1, v2, v3;
            unpack2(acc[i][0], v0, v1); unpack2(acc[i][1], v2, v3);
            *(float4*)&sY[(r0 + i) * 64 + c0] = make_float4(v0, v1, v2, v3);
        }
        __syncthreads();
    }

    for (int it = 1; it < NSIT - 1; ++it) {
        mm_fusedT(sT, sZ, sY, tid);        // T = 1.5I - 0.5*(Z@Y)
        mm_dual<true>(sY, sZ, sT, tid);    // Y<-Y@T, Z<-T@Z
    }
    mm_fusedT(sT, sZ, sY, tid);            // last iteration
    mm_dual<false>(sY, sZ, sT, tid);       // Z<-T@Z only (Y dead)

    const float rinv = 1.0f / sqrtf(nrm);
    float* Aout = g_A + b * 4096;
    for (int idx = tid; idx < 4096; idx += 256) {
        Aout[idx] = 0.5f * ((((idx >> 6) == (idx & 63)) ? 1.f : 0.f) + sZ[idx] * rinv);
    }
}

// ============================================================================
// Launch: 1 init + 50x (NS + fused-update), last fused writes d_out.
// All on default stream; graph-capturable; no allocations; no atomics.
// ============================================================================
extern "C" void kernel_launch(void* const* d_in, const int* in_sizes, int n_in,
                              void* d_out, int out_size) {
    const float* X0 = (const float*)d_in[0];
    float* out = (float*)d_out;
    dim3 grid(NRB, Bn);   // 16 x 32 = 512 CTAs: single wave at >=4 CTA/SM

    ac_kernel<0><<<grid, 128>>>(X0, nullptr);           // W=X0, Gram(X0)
    for (int t = 0; t < MAXIT; ++t) {
        ns_kernel<<<Bn, 256>>>();                       // A_t from Gram(W_t)
        if (t < MAXIT - 1)
            ac_kernel<1><<<grid, 128>>>(X0, nullptr);   // W_{t+1} + Gram
        else
            ac_kernel<2><<<grid, 128>>>(X0, out);       // final relu(W@A) -> out
    }
}

// round 12
// speedup vs baseline: 1.4275x; 1.4275x over previous
#include <cuda_runtime.h>

// ---------------- problem constants ----------------
constexpr int Bn = 32;
constexpr int Pn = 16384;
constexpr int Kn = 64;
constexpr int NTILES = 16;           // 64-row tiles per CTA (single-wave grid)
constexpr int RPC = 64 * NTILES;     // 1024 rows per CTA
constexpr int NRB = Pn / RPC;        // 16 row-blocks per batch -> grid 512
constexpr int MAXIT = 50;
constexpr int NSIT = 8;

// ---------------- device scratch (static; no allocations) ----------------
__device__ float g_W[(size_t)Bn * Pn * Kn];            // 128 MB: current Y' ("W")
__device__ float g_Gpart[(size_t)Bn * NRB * Kn * Kn];  // 8 MB: per-CTA Gram partials
__device__ float g_A[Bn * Kn * Kn];                    // 0.5*(I+S) per batch

// ---------------- packed f32x2 helpers ----------------
typedef unsigned long long f2_t;

__device__ __forceinline__ f2_t pack2(float lo, float hi) {
    f2_t r; asm("mov.b64 %0, {%1, %2};" : "=l"(r) : "f"(lo), "f"(hi)); return r;
}
__device__ __forceinline__ void unpack2(f2_t v, float& lo, float& hi) {
    asm("mov.b64 {%0, %1}, %2;" : "=f"(lo), "=f"(hi) : "l"(v));
}
__device__ __forceinline__ void ffma2(f2_t& d, f2_t a, f2_t b) {
    asm("fma.rn.f32x2 %0, %1, %2, %0;" : "+l"(d) : "l"(a), "l"(b));
}
__device__ __forceinline__ float lane_of(const float4& v, int kk) {
    return (kk == 0) ? v.x : (kk == 1) ? v.y : (kk == 2) ? v.z : v.w;
}

// ============================================================================
// Big fused kernel — CONFLICT-FREE smem mapping.
// MODE 0 (INIT):  W = X0 (copy), Gram partials of W.
// MODE 1 (MID):   Z = relu(W @ A); W' = Z - 0.1*(Z - X0); store W'; Gram(W').
// MODE 2 (FINAL): Z = relu(W @ A); store Z to d_out. No gram.
//
// 128 threads. Thread coords: lane = tid&31, warp = tid>>5,
//   tx = lane&7, tyw = lane>>3.
// Matmul: thread owns rows { warp*16 + 4i + tyw : i=0..3 }  (consecutive rows
//   across the warp per load i -> bank groups 0/16/32/48 at 272B row stride)
// and cols {tx*4..tx*4+3} U {32+tx*4..35+tx*4}  (two float4s at tx*16B offsets
//   -> all 8 bank groups covered, conflict-free).
// Gram: thread owns a-cols { warp*16+tyw*4 .. +3 } and the same split b-cols.
// ============================================================================
template <int MODE>
__global__ __launch_bounds__(128) void ac_kernel(const float* __restrict__ x0,
                                                 float* __restrict__ gout) {
    const int b = blockIdx.y, rb = blockIdx.x;
    const int tid = threadIdx.x;
    const int lane = tid & 31, warp = tid >> 5;
    const int tx = lane & 7;
    const int tyw = lane >> 3;
    const int cA = tx * 4;            // first b-col block
    const int cB = 32 + tx * 4;       // second b-col block
    const int aBase = warp * 16 + tyw * 4;   // gram a-col block (4 consecutive)
    const int rBase = warp * 16 + tyw;       // matmul rows: rBase + 4*i

    __shared__ float sW[64][68];
    __shared__ float sA[64][68];

    const size_t baseRow = (size_t)b * Pn + (size_t)rb * RPC;

    if (MODE != 0) {
        const float4* Ag = (const float4*)(g_A + b * 4096);
        #pragma unroll
        for (int i = tid; i < 1024; i += 128) {
            float4 v = Ag[i];
            *(float4*)&sA[i >> 4][(i & 15) * 4] = v;
        }
    }

    f2_t gacc[4][4];
    #pragma unroll
    for (int i = 0; i < 4; i++)
        #pragma unroll
        for (int j = 0; j < 4; j++) gacc[i][j] = pack2(0.f, 0.f);

    for (int tile = 0; tile < NTILES; ++tile) {
        const size_t trow = baseRow + (size_t)tile * 64;
        __syncthreads();  // previous-tile smem reads complete
        {
            const float* wsrcp = (MODE == 0 ? x0 : (const float*)g_W) + trow * 64;
            const float4* src = (const float4*)wsrcp;
            float4* wdst = (float4*)(g_W + trow * 64);
            #pragma unroll
            for (int i = tid; i < 1024; i += 128) {
                float4 v = src[i];
                *(float4*)&sW[i >> 4][(i & 15) * 4] = v;
                if (MODE == 0) wdst[i] = v;
            }
        }
        __syncthreads();

        if (MODE != 0) {
            // Prefetch X0 epilogue operands BEFORE the matmul (latency hidden
            // under the FFMA2 block). MODE 1 only.
            float4 xpre[4][2];
            if (MODE == 1) {
                #pragma unroll
                for (int i = 0; i < 4; i++) {
                    const float* xr = x0 + (trow + rBase + 4 * i) * 64;
                    xpre[i][0] = *(const float4*)(xr + cA);
                    xpre[i][1] = *(const float4*)(xr + cB);
                }
            }

            // ---- Z-block = (W tile) @ A, conflict-free loads ----
            f2_t acc[4][4];
            #pragma unroll
            for (int i = 0; i < 4; i++)
                #pragma unroll
                for (int j = 0; j < 4; j++) acc[i][j] = pack2(0.f, 0.f);

            #pragma unroll 2
            for (int kb = 0; kb < 16; kb++) {
                float4 w4[4];
                #pragma unroll
                for (int i = 0; i < 4; i++)
                    w4[i] = *(const float4*)&sW[rBase + 4 * i][kb * 4];
                #pragma unroll
                for (int kk = 0; kk < 4; kk++) {
                    const int k = kb * 4 + kk;
                    float4 a0 = *(const float4*)&sA[k][cA];
                    float4 a1 = *(const float4*)&sA[k][cB];
                    f2_t pb0 = pack2(a0.x, a0.y), pb1 = pack2(a0.z, a0.w);
                    f2_t pb2 = pack2(a1.x, a1.y), pb3 = pack2(a1.z, a1.w);
                    #pragma unroll
                    for (int i = 0; i < 4; i++) {
                        float w = lane_of(w4[i], kk);
                        f2_t wp = pack2(w, w);
                        ffma2(acc[i][0], wp, pb0);
                        ffma2(acc[i][1], wp, pb1);
                        ffma2(acc[i][2], wp, pb2);
                        ffma2(acc[i][3], wp, pb3);
                    }
                }
            }

            float wout[4][8];
            #pragma unroll
            for (int i = 0; i < 4; i++) {
                float z[8];
                unpack2(acc[i][0], z[0], z[1]); unpack2(acc[i][1], z[2], z[3]);
                unpack2(acc[i][2], z[4], z[5]); unpack2(acc[i][3], z[6], z[7]);
                #pragma unroll
                for (int j = 0; j < 8; j++) z[j] = fmaxf(z[j], 0.f);
                if (MODE == 1) {
                    float xv[8] = {xpre[i][0].x, xpre[i][0].y, xpre[i][0].z, xpre[i][0].w,
                                   xpre[i][1].x, xpre[i][1].y, xpre[i][1].z, xpre[i][1].w};
                    #pragma unroll
                    for (int j = 0; j < 8; j++)
                        wout[i][j] = z[j] - 0.1f * (z[j] - xv[j]);  // grad step
                } else {
                    #pragma unroll
                    for (int j = 0; j < 8; j++) wout[i][j] = z[j];
                }
            }

            __syncthreads();  // all matmul reads of sW done
            if (MODE == 1) {
                #pragma unroll
                for (int i = 0; i < 4; i++) {
                    const int r = rBase + 4 * i;
                    float4 v0 = make_float4(wout[i][0], wout[i][1], wout[i][2], wout[i][3]);
                    float4 v1 = make_float4(wout[i][4], wout[i][5], wout[i][6], wout[i][7]);
                    *(float4*)&sW[r][cA] = v0;
                    *(float4*)&sW[r][cB] = v1;
                    float* wr = g_W + (trow + r) * 64;
                    *(float4*)(wr + cA) = v0;
                    *(float4*)(wr + cB) = v1;
                }
                __syncthreads();  // W' visible in smem for gram
            } else {  // FINAL: write output
                #pragma unroll
                for (int i = 0; i < 4; i++) {
                    float* orow = gout + (trow + rBase + 4 * i) * 64;
                    *(float4*)(orow + cA) = make_float4(wout[i][0], wout[i][1], wout[i][2], wout[i][3]);
                    *(float4*)(orow + cB) = make_float4(wout[i][4], wout[i][5], wout[i][6], wout[i][7]);
                }
            }
        }

        if (MODE != 2) {
            // ---- Gram accumulate: M[a][b] += sum_r W'[r][a]*W'[r][b] ----
            // wa: 4 addrs at 16B spacing (conflict-free); wb: tx*16B (c-free).
            #pragma unroll 4
            for (int r = 0; r < 64; r++) {
                float4 wa  = *(const float4*)&sW[r][aBase];
                float4 wb0 = *(const float4*)&sW[r][cA];
                float4 wb1 = *(const float4*)&sW[r][cB];
                f2_t pb0 = pack2(wb0.x, wb0.y), pb1 = pack2(wb0.z, wb0.w);
                f2_t pb2 = pack2(wb1.x, wb1.y), pb3 = pack2(wb1.z, wb1.w);
                float av[4] = {wa.x, wa.y, wa.z, wa.w};
                #pragma unroll
                for (int i = 0; i < 4; i++) {
                    f2_t ap = pack2(av[i], av[i]);
                    ffma2(gacc[i][0], ap, pb0);
                    ffma2(gacc[i][1], ap, pb1);
                    ffma2(gacc[i][2], ap, pb2);
                    ffma2(gacc[i][3], ap, pb3);
                }
            }
        }
    }

    if (MODE != 2) {
        float* gp = g_Gpart + ((size_t)(b * NRB + rb)) * 4096;
        #pragma unroll
        for (int i = 0; i < 4; i++) {
            float v[8];
            unpack2(gacc[i][0], v[0], v[1]); unpack2(gacc[i][1], v[2], v[3]);
            unpack2(gacc[i][2], v[4], v[5]); unpack2(gacc[i][3], v[6], v[7]);
            float* row = gp + (aBase + i) * 64;
            *(float4*)(row + cA) = make_float4(v[0], v[1], v[2], v[3]);
            *(float4*)(row + cB) = make_float4(v[4], v[5], v[6], v[7]);
        }
    }
}

// ============================================================================
// Tiny per-batch kernel (UNCHANGED from the passing round-7 kernel).
// ============================================================================

// T = 1.5*I - 0.5*(Z@Y). T distinct from Z,Y -> single trailing sync.
__device__ __forceinline__ void mm_fusedT(float* __restrict__ T,
                                          const float* __restrict__ Z,
                                          const float* __restrict__ Y, int tid) {
    const int tx = tid & 15, ty = tid >> 4;
    const int c0 = tx * 4, r0 = ty * 4;
    f2_t acc[4][2];
    #pragma unroll
    for (int i = 0; i < 4; i++) { acc[i][0] = pack2(0.f, 0.f); acc[i][1] = pack2(0.f, 0.f); }
    #pragma unroll 2
    for (int kb = 0; kb < 16; kb++) {
        float4 a4[4];
        #pragma unroll
        for (int i = 0; i < 4; i++)
            a4[i] = *(const float4*)&Z[(r0 + i) * 64 + kb * 4];
        #pragma unroll
        for (int kk = 0; kk < 4; kk++) {
            float4 b4 = *(const float4*)&Y[(kb * 4 + kk) * 64 + c0];
            f2_t pb0 = pack2(b4.x, b4.y), pb1 = pack2(b4.z, b4.w);
            #pragma unroll
            for (int i = 0; i < 4; i++) {
                float a = lane_of(a4[i], kk);
                f2_t ap = pack2(a, a);
                ffma2(acc[i][0], ap, pb0);
                ffma2(acc[i][1], ap, pb1);
            }
        }
    }
    #pragma unroll
    for (int i = 0; i < 4; i++) {
        float v0, v1, v2, v3;
        unpack2(acc[i][0], v0, v1); unpack2(acc[i][1], v2, v3);
        const int row = r0 + i;
        v0 = ((row == c0 + 0) ? 1.5f : 0.f) - 0.5f * v0;
        v1 = ((row == c0 + 1) ? 1.5f : 0.f) - 0.5f * v1;
        v2 = ((row == c0 + 2) ? 1.5f : 0.f) - 0.5f * v2;
        v3 = ((row == c0 + 3) ? 1.5f : 0.f) - 0.5f * v3;
        *(float4*)&T[row * 64 + c0] = make_float4(v0, v1, v2, v3);
    }
    __syncthreads();
}

// Dual in-place update: Y <- Y@T and Z <- T@Z (independent products, shared pass).
template <bool WITH_Y>
__device__ __forceinline__ void mm_dual(float* __restrict__ Y, float* __restrict__ Z,
                                        const float* __restrict__ T, int tid) {
    const int tx = tid & 15, ty = tid >> 4;
    const int c0 = tx * 4, r0 = ty * 4;
    f2_t accY[4][2], accZ[4][2];
    #pragma unroll
    for (int i = 0; i < 4; i++) {
        accY[i][0] = pack2(0.f, 0.f); accY[i][1] = pack2(0.f, 0.f);
        accZ[i][0] = pack2(0.f, 0.f); accZ[i][1] = pack2(0.f, 0.f);
    }
    #pragma unroll 2
    for (int kb = 0; kb < 16; kb++) {
        float4 aY[4], aZ[4];
        #pragma unroll
        for (int i = 0; i < 4; i++) {
            if (WITH_Y) aY[i] = *(const float4*)&Y[(r0 + i) * 64 + kb * 4];
            aZ[i] = *(const float4*)&T[(r0 + i) * 64 + kb * 4];
        }
        #pragma unroll
        for (int kk = 0; kk < 4; kk++) {
            const int k = kb * 4 + kk;
            float4 bZ = *(const float4*)&Z[k * 64 + c0];
            f2_t zb0 = pack2(bZ.x, bZ.y), zb1 = pack2(bZ.z, bZ.w);
            f2_t yb0, yb1;
            if (WITH_Y) {
                float4 bY = *(const float4*)&T[k * 64 + c0];
                yb0 = pack2(bY.x, bY.y); yb1 = pack2(bY.z, bY.w);
            }
            #pragma unroll
            for (int i = 0; i < 4; i++) {
                float az = lane_of(aZ[i], kk);
                f2_t azp = pack2(az, az);
                ffma2(accZ[i][0], azp, zb0);
                ffma2(accZ[i][1], azp, zb1);
                if (WITH_Y) {
                    float ay = lane_of(aY[i], kk);
                    f2_t ayp = pack2(ay, ay);
                    ffma2(accY[i][0], ayp, yb0);
                    ffma2(accY[i][1], ayp, yb1);
                }
            }
        }
    }
    __syncthreads();  // all reads of Y,Z,T done before in-place writes
    #pragma unroll
    for (int i = 0; i < 4; i++) {
        float v0, v1, v2, v3;
        unpack2(accZ[i][0], v0, v1); unpack2(accZ[i][1], v2, v3);
        *(float4*)&Z[(r0 + i) * 64 + c0] = make_float4(v0, v1, v2, v3);
        if (WITH_Y) {
            unpack2(accY[i][0], v0, v1); unpack2(accY[i][1], v2, v3);
            *(float4*)&Y[(r0 + i) * 64 + c0] = make_float4(v0, v1, v2, v3);
        }
    }
    __syncthreads();
}

__global__ __launch_bounds__(256) void ns_kernel() {
    const int b = blockIdx.x;
    const int tid = threadIdx.x;
    __shared__ float sY[4096];
    __shared__ float sZ[4096];
    __shared__ float sT[4096];  // exactly 48 KB total

    // deterministic partial reduction over 16 row-block partials (float4-wide)
    {
        const float4* gp = (const float4*)(g_Gpart + (size_t)b * NRB * 4096);
        float4* y4 = (float4*)sY;
        for (int idx = tid; idx < 1024; idx += 256) {
            float4 s = make_float4(0.f, 0.f, 0.f, 0.f);
            #pragma unroll
            for (int j = 0; j < NRB; j++) {
                float4 v = gp[(size_t)j * 1024 + idx];
                s.x += v.x; s.y += v.y; s.z += v.z; s.w += v.w;
            }
            y4[idx] = s;
        }
    }
    __syncthreads();

    // trace -> nrm
    float tr = (tid < 64) ? sY[tid * 64 + tid] : 0.f;
    #pragma unroll
    for (int o = 16; o > 0; o >>= 1) tr += __shfl_down_sync(0xffffffffu, tr, o);
    if ((tid & 31) == 0) sT[tid >> 5] = tr;
    __syncthreads();
    const float nrm = sT[0] + sT[1] + sT[2] + sT[3] + sT[4] + sT[5] + sT[6] + sT[7] + 1e-8f;
    __syncthreads();

    // Y0 = M/nrm; iteration 0 shortcut: T = 1.5I - 0.5*Y0 (Z0 = I), Z1 = T
    const float inv = 1.0f / nrm;
    for (int idx = tid; idx < 4096; idx += 256) {
        float y0 = sY[idx] * inv;
        sY[idx] = y0;
        float t0 = (((idx >> 6) == (idx & 63)) ? 1.5f : 0.f) - 0.5f * y0;
        sT[idx] = t0;
        sZ[idx] = t0;
    }
    __syncthreads();
    // Y1 = Y0@T (in place): plain single product.
    {
        const int tx = tid & 15, ty = tid >> 4;
        const int c0 = tx * 4, r0 = ty * 4;
        f2_t acc[4][2];
        #pragma unroll
        for (int i = 0; i < 4; i++) { acc[i][0] = pack2(0.f, 0.f); acc[i][1] = pack2(0.f, 0.f); }
        #pragma unroll 2
        for (int kb = 0; kb < 16; kb++) {
            float4 a4[4];
            #pragma unroll
            for (int i = 0; i < 4; i++)
                a4[i] = *(const float4*)&sY[(r0 + i) * 64 + kb * 4];
            #pragma unroll
            for (int kk = 0; kk < 4; kk++) {
                float4 b4 = *(const float4*)&sT[(kb * 4 + kk) * 64 + c0];
                f2_t pb0 = pack2(b4.x, b4.y), pb1 = pack2(b4.z, b4.w);
                #pragma unroll
                for (int i = 0; i < 4; i++) {
                    float a = lane_of(a4[i], kk);
                    f2_t ap = pack2(a, a);
                    ffma2(acc[i][0], ap, pb0);
                    ffma2(acc[i][1], ap, pb1);
                }
            }
        }
        __syncthreads();
        #pragma unroll
        for (int i = 0; i < 4; i++) {
            float v0, v1, v2, v3;
            unpack2(acc[i][0], v0, v1); unpack2(acc[i][1], v2, v3);
            *(float4*)&sY[(r0 + i) * 64 + c0] = make_float4(v0, v1, v2, v3);
        }
        __syncthreads();
    }

    for (int it = 1; it < NSIT - 1; ++it) {
        mm_fusedT(sT, sZ, sY, tid);        // T = 1.5I - 0.5*(Z@Y)
        mm_dual<true>(sY, sZ, sT, tid);    // Y<-Y@T, Z<-T@Z
    }
    mm_fusedT(sT, sZ, sY, tid);            // last iteration
    mm_dual<false>(sY, sZ, sT, tid);       // Z<-T@Z only (Y dead)

    const float rinv = 1.0f / sqrtf(nrm);
    float* Aout = g_A + b * 4096;
    for (int idx = tid; idx < 4096; idx += 256) {
        Aout[idx] = 0.5f * ((((idx >> 6) == (idx & 63)) ? 1.f : 0.f) + sZ[idx] * rinv);
    }
}

// ============================================================================
// Launch: 1 init + 50x (NS + fused-update), last fused writes d_out.
// ============================================================================
extern "C" void kernel_launch(void* const* d_in, const int* in_sizes, int n_in,
                              void* d_out, int out_size) {
    const float* X0 = (const float*)d_in[0];
    float* out = (float*)d_out;
    dim3 grid(NRB, Bn);   // 16 x 32 = 512 CTAs: single wave at >=4 CTA/SM

    ac_kernel<0><<<grid, 128>>>(X0, nullptr);           // W=X0, Gram(X0)
    for (int t = 0; t < MAXIT; ++t) {
        ns_kernel<<<Bn, 256>>>();                       // A_t from Gram(W_t)
        if (t < MAXIT - 1)
            ac_kernel<1><<<grid, 128>>>(X0, nullptr);   // W_{t+1} + Gram
        else
            ac_kernel<2><<<grid, 128>>>(X0, out);       // final relu(W@A) -> out
    }
}